// round 10
// baseline (speedup 1.0000x reference)
#include <cuda_runtime.h>
#include <cstdint>

typedef unsigned long long u64;

#define HW 3136  // 56*56

__device__ __forceinline__ u64 pack2(float a, float b) {
    u64 r; asm("mov.b64 %0, {%1,%2};" : "=l"(r) : "f"(a), "f"(b)); return r;
}
__device__ __forceinline__ float2 unpack2(u64 a) {
    float2 r; asm("mov.b64 {%0,%1}, %2;" : "=f"(r.x), "=f"(r.y) : "l"(a)); return r;
}
__device__ __forceinline__ u64 fma2(u64 a, u64 b, u64 c) {
    u64 d; asm("fma.rn.f32x2 %0, %1, %2, %3;" : "=l"(d) : "l"(a), "l"(b), "l"(c)); return d;
}
__device__ __forceinline__ void cpa16(uint32_t dst, const void* src) {
    asm volatile("cp.async.cg.shared.global [%0], [%1], 16;" :: "r"(dst), "l"(src));
}
__device__ __forceinline__ void cpa_commit() { asm volatile("cp.async.commit_group;" ::: "memory"); }
__device__ __forceinline__ void cpa_wait0()  { asm volatile("cp.async.wait_group 0;"  ::: "memory"); }
__device__ __forceinline__ void stcs4(float* p, float4 v) {
    asm volatile("st.global.cs.v4.f32 [%0], {%1,%2,%3,%4};"
                 :: "l"(p), "f"(v.x), "f"(v.y), "f"(v.z), "f"(v.w) : "memory");
}

#define NSLOT 11          // source rows m0-2..m0+7 (slots 0..9) + wrap row 55 (slot 10)
#define CCH 2             // channels per chunk (one kk pair)
#define XS_BUF (CCH * NSLOT * 56)   // 1232 floats = 4928 B per buffer
#define NLOAD (CCH * NSLOT * 14)    // 308 float4 per chunk

// ---------------------------------------------------------------------------
// Fused: block = (l, 8-row m chunk). 224 threads = (wq:14, mloc:8, h:2).
// Phase 1: x staged via double-buffered cp.async (1 kk per chunk, 64 chunks);
//   packed f32x2 FMA; T tile kept in smem Ts[mi][ij][64] (edge cols zero).
// Phase 2: 3-tap conv along w; f32x2 packed over adjacent n (shifted pairs),
//   i2 reduction accumulates into the same packed register. Streaming stores.
// Target 6 blocks/SM: smem 33920 B, regs capped 48.
// ---------------------------------------------------------------------------
__global__ __launch_bounds__(224, 6) void fused(const float* __restrict__ x,
                                                const float* __restrict__ w1,
                                                const float* __restrict__ w2,
                                                float* __restrict__ out) {
    __shared__ float xs[2][XS_BUF];   //  9856 B
    __shared__ u64   w1p[768];        //  6144 B  stage-1 weights, (w,w) dup pairs
    __shared__ u64   w2d[192];        //  1536 B  stage-2 weights, (w,w) dup pairs
    __shared__ float Ts[8 * 8 * 64];  // 16384 B  [mi][ij][4+w]

    int tid = threadIdx.x;
    int m0  = blockIdx.x * 8;
    int l   = blockIdx.y;

    // ---- weights + Ts edge zeroing ----
    for (int i = tid; i < 768; i += 224) { float w = w1[i]; w1p[i] = pack2(w, w); }
    if (tid < 192) { float w = w2[tid]; w2d[tid] = pack2(w, w); }
    for (int i = tid; i < 64 * 8; i += 224) {       // 64 rows x 8 edge cols
        int r = i >> 3, c = i & 7;
        Ts[r * 64 + (c < 4 ? c : 56 + c)] = 0.0f;   // cols 0..3 and 60..63
    }

    // ---- thread decode ----
    int wq   = tid % 14;
    int mloc = (tid / 14) % 8;
    int h    = tid / 112;        // i-half in phase 1, j-half in phase 2
    int m    = m0 + mloc;
    int w0   = wq * 4;

    // per-(m,tap) smem slot + validity (stage-1 H taps with +1 circular roll)
    int  slot[3];
    bool val[3];
#pragma unroll
    for (int tap = 0; tap < 3; tap++) {
        int hp    = m + tap - 1;
        val[tap]  = (hp >= 0) && (hp < 56);
        slot[tap] = (hp == 0) ? 10 : (mloc + tap);
    }

    // ---- cooperative-loader precompute: 2 slots/thread ----
    const float* xl = x + (size_t)l * 128 * HW;
    int  goff[2];
    int  soff[2];
    bool lv[2];
#pragma unroll
    for (int k = 0; k < 2; k++) {
        int idx = tid + k * 224;
        lv[k] = idx < NLOAD;
        int ii = lv[k] ? idx : 0;
        int c  = ii / (NSLOT * 14);
        int r  = ii % (NSLOT * 14);
        int s  = r / 14;
        int wf = r % 14;
        int row = (s == 10) ? 55 : min(max(m0 - 2 + s, 0), 55);
        goff[k] = c * HW + row * 56 + wf * 4;
        soff[k] = ((c * NSLOT + s) * 56 + wf * 4) * 4;
    }
    uint32_t xsb[2] = { (uint32_t)__cvta_generic_to_shared(&xs[0][0]),
                        (uint32_t)__cvta_generic_to_shared(&xs[1][0]) };

    u64 acc[4][2];  // [j][w-pair]
#pragma unroll
    for (int j = 0; j < 4; j++) { acc[j][0] = 0ull; acc[j][1] = 0ull; }

    // prefetch chunk 0
#pragma unroll
    for (int k = 0; k < 2; k++)
        if (lv[k]) cpa16(xsb[0] + soff[k], xl + goff[k]);
    cpa_commit();

    // ---- phase 1 main loop: 64 chunks of 2 channels (one kk each) ----
    for (int kk = 0; kk < 64; kk++) {
        cpa_wait0();
        __syncthreads();               // data visible; prev buf free
        if (kk < 63) {
            const float* cb = xl + (size_t)(kk + 1) * CCH * HW;
            uint32_t sb = xsb[(kk + 1) & 1];
#pragma unroll
            for (int k = 0; k < 2; k++)
                if (lv[k]) cpa16(sb + soff[k], cb + goff[k]);
            cpa_commit();
        }
        const float* xb = xs[kk & 1];
#pragma unroll
        for (int tap = 0; tap < 3; tap++) {
            if (val[tap]) {
                ulonglong2 wa = *reinterpret_cast<const ulonglong2*>(&w1p[kk * 12 + tap * 4]);
                ulonglong2 wb = *reinterpret_cast<const ulonglong2*>(&w1p[kk * 12 + tap * 4 + 2]);
                ulonglong2 xp = *reinterpret_cast<const ulonglong2*>(
                    &xb[(h * NSLOT + slot[tap]) * 56 + w0]);
                acc[0][0] = fma2(xp.x, wa.x, acc[0][0]);
                acc[0][1] = fma2(xp.y, wa.x, acc[0][1]);
                acc[1][0] = fma2(xp.x, wa.y, acc[1][0]);
                acc[1][1] = fma2(xp.y, wa.y, acc[1][1]);
                acc[2][0] = fma2(xp.x, wb.x, acc[2][0]);
                acc[2][1] = fma2(xp.y, wb.x, acc[2][1]);
                acc[3][0] = fma2(xp.x, wb.y, acc[3][0]);
                acc[3][1] = fma2(xp.y, wb.y, acc[3][1]);
            }
        }
    }

    // ---- write T tile to smem: Ts[mloc][ij][4 + w] ----
#pragma unroll
    for (int j = 0; j < 4; j++) {
        float2 a0 = unpack2(acc[j][0]);   // w0, w0+1
        float2 a1 = unpack2(acc[j][1]);   // w0+2, w0+3
        int ij = h * 4 + j;
        *reinterpret_cast<float4*>(&Ts[(mloc * 8 + ij) * 64 + 4 + w0]) =
            make_float4(a0.x, a0.y, a1.x, a1.y);
    }
    __syncthreads();

    // ---- phase 2: thread = (mloc, nq=wq, jh=h); n = w0..w0+3, 16 j, 4 oo ----
    float* ob = out + (size_t)l * 128 * HW + m * 56 + w0;

#pragma unroll
    for (int oo = 0; oo < 4; oo++) {
        // shifted n-pairs P[i2][k'] = (t[k'], t[k'+1]), k' = 0..4
        u64 P[2][5];
#pragma unroll
        for (int i2 = 0; i2 < 2; i2++) {
            const float* r = &Ts[(mloc * 8 + i2 * 4 + oo) * 64 + 3 + w0];
            float t0 = r[0], t1 = r[1], t2 = r[2], t3 = r[3], t4 = r[4], t5 = r[5];
            P[i2][0] = pack2(t0, t1);
            P[i2][1] = pack2(t1, t2);
            P[i2][2] = pack2(t2, t3);
            P[i2][3] = pack2(t3, t4);
            P[i2][4] = pack2(t4, t5);
        }

#pragma unroll 4
        for (int jj = 0; jj < 16; jj++) {
            int j = h * 16 + jj;
            // rrA = out(n0,n0+1), rrB = out(n0+2,n0+3); i2 accumulates in-place
            u64 rrA = 0ull, rrB = 0ull;
#pragma unroll
            for (int i2 = 0; i2 < 2; i2++) {
                u64 wk0 = w2d[i2 * 96 + j];
                u64 wk1 = w2d[i2 * 96 + 32 + j];
                u64 wk2 = w2d[i2 * 96 + 64 + j];
                rrA = fma2(P[i2][0], wk0, rrA);
                rrA = fma2(P[i2][1], wk1, rrA);
                rrA = fma2(P[i2][2], wk2, rrA);
                rrB = fma2(P[i2][2], wk0, rrB);
                rrB = fma2(P[i2][3], wk1, rrB);
                rrB = fma2(P[i2][4], wk2, rrB);
            }
            float2 eA = unpack2(rrA);
            float2 eB = unpack2(rrB);
            stcs4(ob + (size_t)(4 * j + oo) * HW, make_float4(eA.x, eA.y, eB.x, eB.y));
        }
    }
}

// ---------------------------------------------------------------------------
extern "C" void kernel_launch(void* const* d_in, const int* in_sizes, int n_in,
                              void* d_out, int out_size) {
    const float* x  = nullptr;
    const float* w1 = nullptr;
    const float* w2 = nullptr;
    for (int i = 0; i < n_in; i++) {
        if (in_sizes[i] == 128 * 128 * 56 * 56) x  = (const float*)d_in[i];
        else if (in_sizes[i] == 64 * 3 * 4)     w1 = (const float*)d_in[i];
        else if (in_sizes[i] == 2 * 3 * 32)     w2 = (const float*)d_in[i];
    }
    if (!x)  x  = (const float*)d_in[0];
    if (!w1) w1 = (const float*)d_in[1];
    if (!w2) w2 = (const float*)d_in[2];

    fused<<<dim3(7, 128), 224>>>(x, w1, w2, (float*)d_out);
}